// round 7
// baseline (speedup 1.0000x reference)
#include <cuda_runtime.h>
#include <cuda_fp16.h>
#include <mma.h>
#include <cstdint>

using namespace nvcuda;

#define NN 100000
#define NE 3200000

// ---------------- static device scratch (no allocations allowed) ----------------
__device__ int     g_deg[NN];
__device__ int     g_off[NN + 1];
__device__ int     g_cursor[NN];
__device__ int2    g_edge[NE];             // (src, bitcast(attn)) sorted by dst
__device__ float   g_hn[(size_t)NN * 128]; // aggregation result (fp32), stride = IN
__device__ __half2 g_xh[(size_t)NN * 64];  // fp16 mirror of x (128 cols)
__device__ __half2 g_hh[(size_t)NN * 64];  // fp16 mirror of current layer output
// fp16 weights
__device__ half g_w1_0[128 * 128];
__device__ half g_w2_0[128 * 128];
__device__ half g_w1_1[128 * 64];
__device__ half g_w2_1[128 * 64];
__device__ half g_w1_2[64 * 32];
__device__ half g_w2_2[64 * 32];

// ---------------- CSR build ----------------
__global__ void k_zero_deg() {
    int i = blockIdx.x * blockDim.x + threadIdx.x;
    if (i < NN) g_deg[i] = 0;
}

__global__ void k_hist(const int* __restrict__ dst) {
    int base = (blockIdx.x * blockDim.x + threadIdx.x) * 4;
    if (base + 3 < NE) {
        int4 d = *(const int4*)&dst[base];
        atomicAdd(&g_deg[d.x], 1);
        atomicAdd(&g_deg[d.y], 1);
        atomicAdd(&g_deg[d.z], 1);
        atomicAdd(&g_deg[d.w], 1);
    } else {
        for (int e = base; e < NE; e++) atomicAdd(&g_deg[dst[e]], 1);
    }
}

// single-block scan: each thread serially owns a contiguous chunk
__global__ void k_scan() {
    __shared__ int part[1024];
    int tid = threadIdx.x;
    const int CH = (NN + 1023) / 1024;
    int beg = tid * CH;
    int end = beg + CH < NN ? beg + CH : NN;
    int s = 0;
    for (int i = beg; i < end; i++) s += g_deg[i];
    part[tid] = s;
    __syncthreads();
    #pragma unroll
    for (int off = 1; off < 1024; off <<= 1) {
        int t = (tid >= off) ? part[tid - off] : 0;
        __syncthreads();
        part[tid] += t;
        __syncthreads();
    }
    int run = tid ? part[tid - 1] : 0;
    for (int i = beg; i < end; i++) {
        int d = g_deg[i];
        g_off[i] = run;
        g_cursor[i] = run;
        run += d;
    }
    if (tid == 1023) g_off[NN] = run;
}

__global__ void k_scatter(const int* __restrict__ src, const int* __restrict__ dst,
                          const float* __restrict__ attn) {
    int base = (blockIdx.x * blockDim.x + threadIdx.x) * 4;
    if (base + 3 < NE) {
        int4   s = *(const int4*)&src[base];
        int4   d = *(const int4*)&dst[base];
        float4 a = *(const float4*)&attn[base];
        int p0 = atomicAdd(&g_cursor[d.x], 1);
        int p1 = atomicAdd(&g_cursor[d.y], 1);
        int p2 = atomicAdd(&g_cursor[d.z], 1);
        int p3 = atomicAdd(&g_cursor[d.w], 1);
        g_edge[p0] = make_int2(s.x, __float_as_int(a.x));
        g_edge[p1] = make_int2(s.y, __float_as_int(a.y));
        g_edge[p2] = make_int2(s.z, __float_as_int(a.z));
        g_edge[p3] = make_int2(s.w, __float_as_int(a.w));
    } else {
        for (int e = base; e < NE; e++) {
            int p = atomicAdd(&g_cursor[dst[e]], 1);
            g_edge[p] = make_int2(src[e], __float_as_int(attn[e]));
        }
    }
}

// ---------------- weight fp32 -> fp16 ----------------
__global__ void k_convw(const float* __restrict__ W, half* __restrict__ Wh, int n) {
    int i = blockIdx.x * blockDim.x + threadIdx.x;
    if (i < n) Wh[i] = __float2half(W[i]);
}

// ---------------- copy x into output cols [0,128) + fp16 mirror ----------------
__global__ void k_copy_x(const float* __restrict__ x, float* __restrict__ out) {
    int t = blockIdx.x * blockDim.x + threadIdx.x;
    if (t < NN * 32) {
        int v = t >> 5, c = t & 31;
        float4 val = ((const float4*)(x + (size_t)v * 128))[c];
        ((float4*)(out + (size_t)v * 352))[c] = val;
        g_xh[(size_t)v * 64 + c * 2]     = __floats2half2_rn(val.x, val.y);
        g_xh[(size_t)v * 64 + c * 2 + 1] = __floats2half2_rn(val.z, val.w);
    }
}

// ---------------- aggregation: warp per dst node, CSR gather of fp16 rows ----------------
template <int VEC>
__global__ void k_agg(const __half2* __restrict__ xin) {
    int gw = (blockIdx.x * blockDim.x + threadIdx.x) >> 5;
    if (gw >= NN) return;
    int lane = threadIdx.x & 31;
    int beg = g_off[gw], end = g_off[gw + 1];

    if (VEC == 4) {
        float4 acc = make_float4(0.f, 0.f, 0.f, 0.f);
        int e = beg;
        for (; e + 3 < end; e += 4) {
            int2 er0 = g_edge[e];
            int2 er1 = g_edge[e + 1];
            int2 er2 = g_edge[e + 2];
            int2 er3 = g_edge[e + 3];
            float2 raw0 = ((const float2*)(xin + (size_t)er0.x * 64))[lane];
            float2 raw1 = ((const float2*)(xin + (size_t)er1.x * 64))[lane];
            float2 raw2 = ((const float2*)(xin + (size_t)er2.x * 64))[lane];
            float2 raw3 = ((const float2*)(xin + (size_t)er3.x * 64))[lane];
            float a0 = __int_as_float(er0.y), a1 = __int_as_float(er1.y);
            float a2 = __int_as_float(er2.y), a3 = __int_as_float(er3.y);
            float2 p;
            p = __half22float2(*(const __half2*)&raw0.x);
            acc.x = fmaf(a0, p.x, acc.x); acc.y = fmaf(a0, p.y, acc.y);
            p = __half22float2(*(const __half2*)&raw0.y);
            acc.z = fmaf(a0, p.x, acc.z); acc.w = fmaf(a0, p.y, acc.w);
            p = __half22float2(*(const __half2*)&raw1.x);
            acc.x = fmaf(a1, p.x, acc.x); acc.y = fmaf(a1, p.y, acc.y);
            p = __half22float2(*(const __half2*)&raw1.y);
            acc.z = fmaf(a1, p.x, acc.z); acc.w = fmaf(a1, p.y, acc.w);
            p = __half22float2(*(const __half2*)&raw2.x);
            acc.x = fmaf(a2, p.x, acc.x); acc.y = fmaf(a2, p.y, acc.y);
            p = __half22float2(*(const __half2*)&raw2.y);
            acc.z = fmaf(a2, p.x, acc.z); acc.w = fmaf(a2, p.y, acc.w);
            p = __half22float2(*(const __half2*)&raw3.x);
            acc.x = fmaf(a3, p.x, acc.x); acc.y = fmaf(a3, p.y, acc.y);
            p = __half22float2(*(const __half2*)&raw3.y);
            acc.z = fmaf(a3, p.x, acc.z); acc.w = fmaf(a3, p.y, acc.w);
        }
        for (; e < end; e++) {
            int2 er = g_edge[e];
            float2 raw = ((const float2*)(xin + (size_t)er.x * 64))[lane];
            float a = __int_as_float(er.y);
            float2 p0 = __half22float2(*(const __half2*)&raw.x);
            float2 p1 = __half22float2(*(const __half2*)&raw.y);
            acc.x = fmaf(a, p0.x, acc.x); acc.y = fmaf(a, p0.y, acc.y);
            acc.z = fmaf(a, p1.x, acc.z); acc.w = fmaf(a, p1.y, acc.w);
        }
        *(float4*)(&g_hn[(size_t)gw * 128 + lane * 4]) = acc;
    } else {
        float2 acc = make_float2(0.f, 0.f);
        int e = beg;
        for (; e + 3 < end; e += 4) {
            int2 er0 = g_edge[e];
            int2 er1 = g_edge[e + 1];
            int2 er2 = g_edge[e + 2];
            int2 er3 = g_edge[e + 3];
            __half2 h0 = xin[(size_t)er0.x * 32 + lane];
            __half2 h1 = xin[(size_t)er1.x * 32 + lane];
            __half2 h2 = xin[(size_t)er2.x * 32 + lane];
            __half2 h3 = xin[(size_t)er3.x * 32 + lane];
            float2 p;
            p = __half22float2(h0); float a0 = __int_as_float(er0.y);
            acc.x = fmaf(a0, p.x, acc.x); acc.y = fmaf(a0, p.y, acc.y);
            p = __half22float2(h1); float a1 = __int_as_float(er1.y);
            acc.x = fmaf(a1, p.x, acc.x); acc.y = fmaf(a1, p.y, acc.y);
            p = __half22float2(h2); float a2 = __int_as_float(er2.y);
            acc.x = fmaf(a2, p.x, acc.x); acc.y = fmaf(a2, p.y, acc.y);
            p = __half22float2(h3); float a3 = __int_as_float(er3.y);
            acc.x = fmaf(a3, p.x, acc.x); acc.y = fmaf(a3, p.y, acc.y);
        }
        for (; e < end; e++) {
            int2 er = g_edge[e];
            __half2 h = xin[(size_t)er.x * 32 + lane];
            float a = __int_as_float(er.y);
            float2 p = __half22float2(h);
            acc.x = fmaf(a, p.x, acc.x); acc.y = fmaf(a, p.y, acc.y);
        }
        *(float2*)(&g_hn[(size_t)gw * 64 + lane * 2]) = acc;
    }
}

// ---------------- fused bi-interaction via wmma (HMMA) ----------------
// 128 threads = 4 warps; block tile BM=64 nodes x BN cols; warp tile 32 x BN/2.
template <int IN, int OUT, int BN>
__global__ void __launch_bounds__(128)
k_fuse_mma(const float* __restrict__ xin, int xstride,
           const half* __restrict__ W1h, const float* __restrict__ b1,
           const half* __restrict__ W2h, const float* __restrict__ b2,
           float* __restrict__ out, int outcol, __half2* __restrict__ hh) {
    constexpr int BM = 64;
    constexpr int NF = BN / 32;                // 16-wide n-frags per warp
    constexpr size_t OPER_BYTES = (size_t)2 * BM * IN * sizeof(half);
    constexpr size_t EPI_BYTES  = (size_t)2 * BM * BN * sizeof(float);
    constexpr size_t SBYTES = OPER_BYTES > EPI_BYTES ? OPER_BYTES : EPI_BYTES;
    __shared__ __align__(16) char sm[SBYTES];
    half*  s_s = (half*)sm;                    // [BM][IN]
    half*  s_p = s_s + (size_t)BM * IN;        // [BM][IN]
    float* o1  = (float*)sm;                   // [BM][BN] (aliases s_s/s_p after sync)
    float* o2  = o1 + (size_t)BM * BN;

    int tid = threadIdx.x;
    int wid = tid >> 5;
    int v0 = blockIdx.x * BM;
    int j0 = blockIdx.y * BN;

    // build S = x+h, P = x*h (fp16)
    for (int i = tid; i < BM * (IN / 2); i += 128) {
        int n = i / (IN / 2), k2 = i % (IN / 2);
        int v = v0 + n;
        float2 xv = make_float2(0.f, 0.f), hv = make_float2(0.f, 0.f);
        if (v < NN) {
            xv = *(const float2*)&xin[(size_t)v * xstride + k2 * 2];
            hv = *(const float2*)&g_hn[(size_t)v * IN + k2 * 2];
        }
        *(__half2*)&s_s[(size_t)n * IN + k2 * 2] = __floats2half2_rn(xv.x + hv.x, xv.y + hv.y);
        *(__half2*)&s_p[(size_t)n * IN + k2 * 2] = __floats2half2_rn(xv.x * hv.x, xv.y * hv.y);
    }
    __syncthreads();

    int wm = wid >> 1;  // 0..1 : row group
    int wn = wid & 1;   // 0..1 : col group

    wmma::fragment<wmma::accumulator, 16, 16, 16, float> acc1[2][NF], acc2[2][NF];
    #pragma unroll
    for (int mi = 0; mi < 2; mi++)
        #pragma unroll
        for (int ni = 0; ni < NF; ni++) {
            wmma::fill_fragment(acc1[mi][ni], 0.f);
            wmma::fill_fragment(acc2[mi][ni], 0.f);
        }

    for (int kc = 0; kc < IN; kc += 16) {
        wmma::fragment<wmma::matrix_a, 16, 16, 16, half, wmma::row_major> a1[2], a2[2];
        #pragma unroll
        for (int mi = 0; mi < 2; mi++) {
            wmma::load_matrix_sync(a1[mi], &s_s[(size_t)(wm * 32 + mi * 16) * IN + kc], IN);
            wmma::load_matrix_sync(a2[mi], &s_p[(size_t)(wm * 32 + mi * 16) * IN + kc], IN);
        }
        #pragma unroll
        for (int ni = 0; ni < NF; ni++) {
            int j = j0 + wn * (BN / 2) + ni * 16;
            wmma::fragment<wmma::matrix_b, 16, 16, 16, half, wmma::row_major> bf1, bf2;
            wmma::load_matrix_sync(bf1, &W1h[(size_t)kc * OUT + j], OUT);
            wmma::load_matrix_sync(bf2, &W2h[(size_t)kc * OUT + j], OUT);
            #pragma unroll
            for (int mi = 0; mi < 2; mi++) {
                wmma::mma_sync(acc1[mi][ni], a1[mi], bf1, acc1[mi][ni]);
                wmma::mma_sync(acc2[mi][ni], a2[mi], bf2, acc2[mi][ni]);
            }
        }
    }

    __syncthreads();  // operand tiles dead; reuse as epilogue buffers
    #pragma unroll
    for (int mi = 0; mi < 2; mi++)
        #pragma unroll
        for (int ni = 0; ni < NF; ni++) {
            int r = wm * 32 + mi * 16;
            int c = wn * (BN / 2) + ni * 16;
            wmma::store_matrix_sync(&o1[(size_t)r * BN + c], acc1[mi][ni], BN, wmma::mem_row_major);
            wmma::store_matrix_sync(&o2[(size_t)r * BN + c], acc2[mi][ni], BN, wmma::mem_row_major);
        }
    __syncthreads();

    for (int i = tid; i < BM * (BN / 2); i += 128) {
        int n = i / (BN / 2), j2 = i % (BN / 2);
        int v = v0 + n;
        if (v < NN) {
            int j = j2 * 2;
            float r1a = o1[(size_t)n * BN + j]     + b1[j0 + j];
            float r1b = o1[(size_t)n * BN + j + 1] + b1[j0 + j + 1];
            float r2a = o2[(size_t)n * BN + j]     + b2[j0 + j];
            float r2b = o2[(size_t)n * BN + j + 1] + b2[j0 + j + 1];
            r1a = r1a > 0.f ? r1a : 0.01f * r1a;
            r1b = r1b > 0.f ? r1b : 0.01f * r1b;
            r2a = r2a > 0.f ? r2a : 0.01f * r2a;
            r2b = r2b > 0.f ? r2b : 0.01f * r2b;
            float ra = r1a + r2a, rb = r1b + r2b;
            *(float2*)&out[(size_t)v * 352 + outcol + j0 + j] = make_float2(ra, rb);
            if (hh) hh[(size_t)v * (OUT / 2) + ((j0 + j) >> 1)] = __floats2half2_rn(ra, rb);
        }
    }
}

// ---------------- launch ----------------
extern "C" void kernel_launch(void* const* d_in, const int* in_sizes, int n_in,
                              void* d_out, int out_size) {
    const float* x    = (const float*)d_in[0];
    const int*   src  = (const int*)d_in[1];
    const int*   dst  = (const int*)d_in[2];
    const float* attn = (const float*)d_in[3];
    const float* W1_0 = (const float*)d_in[4];
    const float* b1_0 = (const float*)d_in[5];
    const float* W2_0 = (const float*)d_in[6];
    const float* b2_0 = (const float*)d_in[7];
    const float* W1_1 = (const float*)d_in[8];
    const float* b1_1 = (const float*)d_in[9];
    const float* W2_1 = (const float*)d_in[10];
    const float* b2_1 = (const float*)d_in[11];
    const float* W1_2 = (const float*)d_in[12];
    const float* b1_2 = (const float*)d_in[13];
    const float* W2_2 = (const float*)d_in[14];
    const float* b2_2 = (const float*)d_in[15];
    float* out = (float*)d_out;

    __half2 *xh, *hh;
    half *w1_0, *w2_0, *w1_1, *w2_1, *w1_2, *w2_2;
    cudaGetSymbolAddress((void**)&xh, g_xh);
    cudaGetSymbolAddress((void**)&hh, g_hh);
    cudaGetSymbolAddress((void**)&w1_0, g_w1_0);
    cudaGetSymbolAddress((void**)&w2_0, g_w2_0);
    cudaGetSymbolAddress((void**)&w1_1, g_w1_1);
    cudaGetSymbolAddress((void**)&w2_1, g_w2_1);
    cudaGetSymbolAddress((void**)&w1_2, g_w1_2);
    cudaGetSymbolAddress((void**)&w2_2, g_w2_2);

    const int aggBlocks = (NN * 32 + 255) / 256;
    const int fuseGrid = (NN + 63) / 64;

    // CSR build (launches 1-3)
    k_zero_deg<<<(NN + 255) / 256, 256>>>();
    k_hist<<<(NE / 4 + 255) / 256, 256>>>(dst);
    k_scan<<<1, 1024>>>();

    // DIAGNOSTIC: duplicate fuse launches at positions 4-6. The ncu capture has
    // consistently landed on the 4th kernel launch, so fuse0_dup gets profiled.
    // They read stale (previous-replay / garbage) g_hn, out, weights; every
    // location they write is fully overwritten by the real launches below, so
    // the final output is unchanged. dur_us - 762 == fuse_total.
    {
        dim3 g(fuseGrid, 2);
        k_fuse_mma<128, 128, 64><<<g, 128>>>(x, 128, w1_0, b1_0, w2_0, b2_0, out, 128, hh);
    }
    {
        dim3 g(fuseGrid, 1);
        k_fuse_mma<128, 64, 64><<<g, 128>>>(out + 128, 352, w1_1, b1_1, w2_1, b2_1, out, 256, hh);
    }
    {
        dim3 g(fuseGrid, 1);
        k_fuse_mma<64, 32, 32><<<g, 128>>>(out + 256, 352, w1_2, b1_2, w2_2, b2_2, out, 320, nullptr);
    }

    k_scatter<<<(NE / 4 + 255) / 256, 256>>>(src, dst, attn);

    // fp16 weights
    k_convw<<<(128 * 128 + 255) / 256, 256>>>(W1_0, w1_0, 128 * 128);
    k_convw<<<(128 * 128 + 255) / 256, 256>>>(W2_0, w2_0, 128 * 128);
    k_convw<<<(128 * 64 + 255) / 256, 256>>>(W1_1, w1_1, 128 * 64);
    k_convw<<<(128 * 64 + 255) / 256, 256>>>(W2_1, w2_1, 128 * 64);
    k_convw<<<(64 * 32 + 255) / 256, 256>>>(W1_2, w1_2, 64 * 32);
    k_convw<<<(64 * 32 + 255) / 256, 256>>>(W2_2, w2_2, 64 * 32);

    // output cols [0,128) = x ; fp16 mirror of x
    k_copy_x<<<(NN * 32 + 255) / 256, 256>>>(x, out);

    // layer 0: IN=128 -> OUT=128
    k_agg<4><<<aggBlocks, 256>>>(xh);
    {
        dim3 g(fuseGrid, 2);
        k_fuse_mma<128, 128, 64><<<g, 128>>>(x, 128, w1_0, b1_0, w2_0, b2_0, out, 128, hh);
    }
    // layer 1: IN=128 -> OUT=64
    k_agg<4><<<aggBlocks, 256>>>(hh);
    {
        dim3 g(fuseGrid, 1);
        k_fuse_mma<128, 64, 64><<<g, 128>>>(out + 128, 352, w1_1, b1_1, w2_1, b2_1, out, 256, hh);
    }
    // layer 2: IN=64 -> OUT=32
    k_agg<2><<<aggBlocks, 256>>>(hh);
    {
        dim3 g(fuseGrid, 1);
        k_fuse_mma<64, 32, 32><<<g, 128>>>(out + 256, 352, w1_2, b1_2, w2_2, b2_2, out, 320, nullptr);
    }
}

// round 10
// speedup vs baseline: 1.2905x; 1.2905x over previous
#include <cuda_runtime.h>
#include <cuda_fp16.h>
#include <mma.h>
#include <cstdint>

using namespace nvcuda;

#define NN 100000
#define NE 3200000

// ---------------- static device scratch (no allocations allowed) ----------------
__device__ int     g_deg[NN];
__device__ int     g_off[NN + 1];
__device__ int     g_cursor[NN];
__device__ int2    g_edge[NE];             // (src, bitcast(attn)) sorted by dst
__device__ float   g_hn[(size_t)NN * 128]; // aggregation result (fp32), stride = IN
__device__ __half2 g_xh[(size_t)NN * 64];  // fp16 mirror of x (128 cols)
__device__ __half2 g_hh[(size_t)NN * 64];  // fp16 mirror of current layer output
// fp16 weights
__device__ half g_w1_0[128 * 128];
__device__ half g_w2_0[128 * 128];
__device__ half g_w1_1[128 * 64];
__device__ half g_w2_1[128 * 64];
__device__ half g_w1_2[64 * 32];
__device__ half g_w2_2[64 * 32];

// ---------------- CSR build ----------------
__global__ void k_zero_deg() {
    int i = blockIdx.x * blockDim.x + threadIdx.x;
    if (i < NN) g_deg[i] = 0;
}

__global__ void k_hist(const int* __restrict__ dst) {
    int base = (blockIdx.x * blockDim.x + threadIdx.x) * 4;
    if (base + 3 < NE) {
        int4 d = *(const int4*)&dst[base];
        atomicAdd(&g_deg[d.x], 1);
        atomicAdd(&g_deg[d.y], 1);
        atomicAdd(&g_deg[d.z], 1);
        atomicAdd(&g_deg[d.w], 1);
    } else {
        for (int e = base; e < NE; e++) atomicAdd(&g_deg[dst[e]], 1);
    }
}

// single-block scan: each thread serially owns a contiguous chunk
__global__ void k_scan() {
    __shared__ int part[1024];
    int tid = threadIdx.x;
    const int CH = (NN + 1023) / 1024;
    int beg = tid * CH;
    int end = beg + CH < NN ? beg + CH : NN;
    int s = 0;
    for (int i = beg; i < end; i++) s += g_deg[i];
    part[tid] = s;
    __syncthreads();
    #pragma unroll
    for (int off = 1; off < 1024; off <<= 1) {
        int t = (tid >= off) ? part[tid - off] : 0;
        __syncthreads();
        part[tid] += t;
        __syncthreads();
    }
    int run = tid ? part[tid - 1] : 0;
    for (int i = beg; i < end; i++) {
        int d = g_deg[i];
        g_off[i] = run;
        g_cursor[i] = run;
        run += d;
    }
    if (tid == 1023) g_off[NN] = run;
}

__global__ void k_scatter(const int* __restrict__ src, const int* __restrict__ dst,
                          const float* __restrict__ attn) {
    int base = (blockIdx.x * blockDim.x + threadIdx.x) * 4;
    if (base + 3 < NE) {
        int4   s = *(const int4*)&src[base];
        int4   d = *(const int4*)&dst[base];
        float4 a = *(const float4*)&attn[base];
        int p0 = atomicAdd(&g_cursor[d.x], 1);
        int p1 = atomicAdd(&g_cursor[d.y], 1);
        int p2 = atomicAdd(&g_cursor[d.z], 1);
        int p3 = atomicAdd(&g_cursor[d.w], 1);
        g_edge[p0] = make_int2(s.x, __float_as_int(a.x));
        g_edge[p1] = make_int2(s.y, __float_as_int(a.y));
        g_edge[p2] = make_int2(s.z, __float_as_int(a.z));
        g_edge[p3] = make_int2(s.w, __float_as_int(a.w));
    } else {
        for (int e = base; e < NE; e++) {
            int p = atomicAdd(&g_cursor[dst[e]], 1);
            g_edge[p] = make_int2(src[e], __float_as_int(attn[e]));
        }
    }
}

// ---------------- weight fp32 -> fp16 ----------------
__global__ void k_convw(const float* __restrict__ W, half* __restrict__ Wh, int n) {
    int i = blockIdx.x * blockDim.x + threadIdx.x;
    if (i < n) Wh[i] = __float2half(W[i]);
}

// ---------------- copy x into output cols [0,128) + fp16 mirror ----------------
__global__ void k_copy_x(const float* __restrict__ x, float* __restrict__ out) {
    int t = blockIdx.x * blockDim.x + threadIdx.x;
    if (t < NN * 32) {
        int v = t >> 5, c = t & 31;
        float4 val = ((const float4*)(x + (size_t)v * 128))[c];
        ((float4*)(out + (size_t)v * 352))[c] = val;
        g_xh[(size_t)v * 64 + c * 2]     = __floats2half2_rn(val.x, val.y);
        g_xh[(size_t)v * 64 + c * 2 + 1] = __floats2half2_rn(val.z, val.w);
    }
}

// ---------------- aggregation: warp per dst node, CSR gather of fp16 rows ----------------
template <int VEC>
__global__ void k_agg(const __half2* __restrict__ xin) {
    int gw = (blockIdx.x * blockDim.x + threadIdx.x) >> 5;
    if (gw >= NN) return;
    int lane = threadIdx.x & 31;
    int beg = g_off[gw], end = g_off[gw + 1];

    if (VEC == 4) {
        float4 acc = make_float4(0.f, 0.f, 0.f, 0.f);
        int e = beg;
        for (; e + 3 < end; e += 4) {
            int2 er0 = g_edge[e];
            int2 er1 = g_edge[e + 1];
            int2 er2 = g_edge[e + 2];
            int2 er3 = g_edge[e + 3];
            float2 raw0 = ((const float2*)(xin + (size_t)er0.x * 64))[lane];
            float2 raw1 = ((const float2*)(xin + (size_t)er1.x * 64))[lane];
            float2 raw2 = ((const float2*)(xin + (size_t)er2.x * 64))[lane];
            float2 raw3 = ((const float2*)(xin + (size_t)er3.x * 64))[lane];
            float a0 = __int_as_float(er0.y), a1 = __int_as_float(er1.y);
            float a2 = __int_as_float(er2.y), a3 = __int_as_float(er3.y);
            float2 p;
            p = __half22float2(*(const __half2*)&raw0.x);
            acc.x = fmaf(a0, p.x, acc.x); acc.y = fmaf(a0, p.y, acc.y);
            p = __half22float2(*(const __half2*)&raw0.y);
            acc.z = fmaf(a0, p.x, acc.z); acc.w = fmaf(a0, p.y, acc.w);
            p = __half22float2(*(const __half2*)&raw1.x);
            acc.x = fmaf(a1, p.x, acc.x); acc.y = fmaf(a1, p.y, acc.y);
            p = __half22float2(*(const __half2*)&raw1.y);
            acc.z = fmaf(a1, p.x, acc.z); acc.w = fmaf(a1, p.y, acc.w);
            p = __half22float2(*(const __half2*)&raw2.x);
            acc.x = fmaf(a2, p.x, acc.x); acc.y = fmaf(a2, p.y, acc.y);
            p = __half22float2(*(const __half2*)&raw2.y);
            acc.z = fmaf(a2, p.x, acc.z); acc.w = fmaf(a2, p.y, acc.w);
            p = __half22float2(*(const __half2*)&raw3.x);
            acc.x = fmaf(a3, p.x, acc.x); acc.y = fmaf(a3, p.y, acc.y);
            p = __half22float2(*(const __half2*)&raw3.y);
            acc.z = fmaf(a3, p.x, acc.z); acc.w = fmaf(a3, p.y, acc.w);
        }
        for (; e < end; e++) {
            int2 er = g_edge[e];
            float2 raw = ((const float2*)(xin + (size_t)er.x * 64))[lane];
            float a = __int_as_float(er.y);
            float2 p0 = __half22float2(*(const __half2*)&raw.x);
            float2 p1 = __half22float2(*(const __half2*)&raw.y);
            acc.x = fmaf(a, p0.x, acc.x); acc.y = fmaf(a, p0.y, acc.y);
            acc.z = fmaf(a, p1.x, acc.z); acc.w = fmaf(a, p1.y, acc.w);
        }
        *(float4*)(&g_hn[(size_t)gw * 128 + lane * 4]) = acc;
    } else {
        float2 acc = make_float2(0.f, 0.f);
        int e = beg;
        for (; e + 3 < end; e += 4) {
            int2 er0 = g_edge[e];
            int2 er1 = g_edge[e + 1];
            int2 er2 = g_edge[e + 2];
            int2 er3 = g_edge[e + 3];
            __half2 h0 = xin[(size_t)er0.x * 32 + lane];
            __half2 h1 = xin[(size_t)er1.x * 32 + lane];
            __half2 h2 = xin[(size_t)er2.x * 32 + lane];
            __half2 h3 = xin[(size_t)er3.x * 32 + lane];
            float2 p;
            p = __half22float2(h0); float a0 = __int_as_float(er0.y);
            acc.x = fmaf(a0, p.x, acc.x); acc.y = fmaf(a0, p.y, acc.y);
            p = __half22float2(h1); float a1 = __int_as_float(er1.y);
            acc.x = fmaf(a1, p.x, acc.x); acc.y = fmaf(a1, p.y, acc.y);
            p = __half22float2(h2); float a2 = __int_as_float(er2.y);
            acc.x = fmaf(a2, p.x, acc.x); acc.y = fmaf(a2, p.y, acc.y);
            p = __half22float2(h3); float a3 = __int_as_float(er3.y);
            acc.x = fmaf(a3, p.x, acc.x); acc.y = fmaf(a3, p.y, acc.y);
        }
        for (; e < end; e++) {
            int2 er = g_edge[e];
            __half2 h = xin[(size_t)er.x * 32 + lane];
            float a = __int_as_float(er.y);
            float2 p = __half22float2(h);
            acc.x = fmaf(a, p.x, acc.x); acc.y = fmaf(a, p.y, acc.y);
        }
        *(float2*)(&g_hn[(size_t)gw * 64 + lane * 2]) = acc;
    }
}

// ---------------- fused bi-interaction v2: smem-staged weights, multi-tile ----------------
// Block: 128 threads / 4 warps. Stages W1/W2 slice [IN x BN] in smem ONCE, then loops
// over NT node tiles of 64 nodes. Warp layout: wm in {0,1} (32 rows), wn in {0,1} (BN/2 cols).
// Epilogue chunked per 32-row group, aliased over the dead operand tiles.
template <int IN, int OUT, int BN, int NT>
__global__ void __launch_bounds__(128)
k_fuse2(const float* __restrict__ xin, int xstride,
        const half* __restrict__ W1h, const float* __restrict__ b1,
        const half* __restrict__ W2h, const float* __restrict__ b2,
        float* __restrict__ out, int outcol, __half2* __restrict__ hh) {
    constexpr int BM = 64;
    constexpr int CW = BN / 2;            // cols per warp
    constexpr int NF = CW / 16;           // 16-col frags per warp
    constexpr size_t W_BYTES    = (size_t)2 * IN * BN * sizeof(half);
    constexpr size_t OPER_BYTES = (size_t)2 * BM * IN * sizeof(half);
    constexpr size_t EPI_BYTES  = (size_t)2 * 32 * BN * sizeof(float);
    constexpr size_t UNION_BYTES = OPER_BYTES > EPI_BYTES ? OPER_BYTES : EPI_BYTES;

    extern __shared__ __align__(16) char sm[];
    half*  sw1 = (half*)sm;                       // [IN][BN]
    half*  sw2 = sw1 + (size_t)IN * BN;           // [IN][BN]
    char*  un  = sm + W_BYTES;
    half*  s_s = (half*)un;                       // [BM][IN]
    half*  s_p = s_s + (size_t)BM * IN;           // [BM][IN]
    float* o1  = (float*)un;                      // [32][BN] epilogue chunk
    float* o2  = o1 + (size_t)32 * BN;

    int tid = threadIdx.x;
    int wid = tid >> 5;
    int j0 = blockIdx.y * BN;
    int wm = wid >> 1;
    int wn = wid & 1;

    // ---- stage weight slice (once per block), 16B vector copies ----
    constexpr int ROWV = BN / 8;  // uint4 per row
    for (int i = tid; i < IN * ROWV; i += 128) {
        int r = i / ROWV, c = i % ROWV;
        ((uint4*)&sw1[(size_t)r * BN])[c] = ((const uint4*)&W1h[(size_t)r * OUT + j0])[c];
        ((uint4*)&sw2[(size_t)r * BN])[c] = ((const uint4*)&W2h[(size_t)r * OUT + j0])[c];
    }

    for (int t = 0; t < NT; t++) {
        int v0 = (blockIdx.x * NT + t) * BM;
        if (v0 >= NN) break;
        __syncthreads();  // weights staged / previous epilogue reads done

        // ---- build S = x+h, P = x*h (fp16) ----
        for (int i = tid; i < BM * (IN / 2); i += 128) {
            int n = i / (IN / 2), k2 = i % (IN / 2);
            int v = v0 + n;
            float2 xv = make_float2(0.f, 0.f), hv = make_float2(0.f, 0.f);
            if (v < NN) {
                xv = *(const float2*)&xin[(size_t)v * xstride + k2 * 2];
                hv = *(const float2*)&g_hn[(size_t)v * IN + k2 * 2];
            }
            *(__half2*)&s_s[(size_t)n * IN + k2 * 2] = __floats2half2_rn(xv.x + hv.x, xv.y + hv.y);
            *(__half2*)&s_p[(size_t)n * IN + k2 * 2] = __floats2half2_rn(xv.x * hv.x, xv.y * hv.y);
        }
        __syncthreads();

        // ---- mainloop: all operands in smem ----
        wmma::fragment<wmma::accumulator, 16, 16, 16, float> acc1[2][NF], acc2[2][NF];
        #pragma unroll
        for (int mi = 0; mi < 2; mi++)
            #pragma unroll
            for (int ni = 0; ni < NF; ni++) {
                wmma::fill_fragment(acc1[mi][ni], 0.f);
                wmma::fill_fragment(acc2[mi][ni], 0.f);
            }

        for (int kc = 0; kc < IN; kc += 16) {
            wmma::fragment<wmma::matrix_a, 16, 16, 16, half, wmma::row_major> a1[2], a2[2];
            #pragma unroll
            for (int mi = 0; mi < 2; mi++) {
                wmma::load_matrix_sync(a1[mi], &s_s[(size_t)(wm * 32 + mi * 16) * IN + kc], IN);
                wmma::load_matrix_sync(a2[mi], &s_p[(size_t)(wm * 32 + mi * 16) * IN + kc], IN);
            }
            #pragma unroll
            for (int ni = 0; ni < NF; ni++) {
                int c = wn * CW + ni * 16;
                wmma::fragment<wmma::matrix_b, 16, 16, 16, half, wmma::row_major> bf1, bf2;
                wmma::load_matrix_sync(bf1, &sw1[(size_t)kc * BN + c], BN);
                wmma::load_matrix_sync(bf2, &sw2[(size_t)kc * BN + c], BN);
                #pragma unroll
                for (int mi = 0; mi < 2; mi++) {
                    wmma::mma_sync(acc1[mi][ni], a1[mi], bf1, acc1[mi][ni]);
                    wmma::mma_sync(acc2[mi][ni], a2[mi], bf2, acc2[mi][ni]);
                }
            }
        }

        // ---- epilogue: per 32-row chunk, aliased over operand tiles ----
        #pragma unroll
        for (int g = 0; g < 2; g++) {
            __syncthreads();  // union region free (operands dead / prev chunk written out)
            if (wm == g) {
                #pragma unroll
                for (int mi = 0; mi < 2; mi++)
                    #pragma unroll
                    for (int ni = 0; ni < NF; ni++) {
                        int r = mi * 16;              // row within chunk
                        int c = wn * CW + ni * 16;
                        wmma::store_matrix_sync(&o1[(size_t)r * BN + c], acc1[mi][ni], BN, wmma::mem_row_major);
                        wmma::store_matrix_sync(&o2[(size_t)r * BN + c], acc2[mi][ni], BN, wmma::mem_row_major);
                    }
            }
            __syncthreads();
            for (int i = tid; i < 32 * (BN / 2); i += 128) {
                int nr = i / (BN / 2), j2 = i % (BN / 2);
                int v = v0 + g * 32 + nr;
                if (v < NN) {
                    int j = j2 * 2;
                    float r1a = o1[(size_t)nr * BN + j]     + b1[j0 + j];
                    float r1b = o1[(size_t)nr * BN + j + 1] + b1[j0 + j + 1];
                    float r2a = o2[(size_t)nr * BN + j]     + b2[j0 + j];
                    float r2b = o2[(size_t)nr * BN + j + 1] + b2[j0 + j + 1];
                    r1a = r1a > 0.f ? r1a : 0.01f * r1a;
                    r1b = r1b > 0.f ? r1b : 0.01f * r1b;
                    r2a = r2a > 0.f ? r2a : 0.01f * r2a;
                    r2b = r2b > 0.f ? r2b : 0.01f * r2b;
                    float ra = r1a + r2a, rb = r1b + r2b;
                    *(float2*)&out[(size_t)v * 352 + outcol + j0 + j] = make_float2(ra, rb);
                    if (hh) hh[(size_t)v * (OUT / 2) + ((j0 + j) >> 1)] = __floats2half2_rn(ra, rb);
                }
            }
        }
    }
}

// ---------------- launch ----------------
extern "C" void kernel_launch(void* const* d_in, const int* in_sizes, int n_in,
                              void* d_out, int out_size) {
    const float* x    = (const float*)d_in[0];
    const int*   src  = (const int*)d_in[1];
    const int*   dst  = (const int*)d_in[2];
    const float* attn = (const float*)d_in[3];
    const float* W1_0 = (const float*)d_in[4];
    const float* b1_0 = (const float*)d_in[5];
    const float* W2_0 = (const float*)d_in[6];
    const float* b2_0 = (const float*)d_in[7];
    const float* W1_1 = (const float*)d_in[8];
    const float* b1_1 = (const float*)d_in[9];
    const float* W2_1 = (const float*)d_in[10];
    const float* b2_1 = (const float*)d_in[11];
    const float* W1_2 = (const float*)d_in[12];
    const float* b1_2 = (const float*)d_in[13];
    const float* W2_2 = (const float*)d_in[14];
    const float* b2_2 = (const float*)d_in[15];
    float* out = (float*)d_out;

    __half2 *xh, *hh;
    half *w1_0, *w2_0, *w1_1, *w2_1, *w1_2, *w2_2;
    cudaGetSymbolAddress((void**)&xh, g_xh);
    cudaGetSymbolAddress((void**)&hh, g_hh);
    cudaGetSymbolAddress((void**)&w1_0, g_w1_0);
    cudaGetSymbolAddress((void**)&w2_0, g_w2_0);
    cudaGetSymbolAddress((void**)&w1_1, g_w1_1);
    cudaGetSymbolAddress((void**)&w2_1, g_w2_1);
    cudaGetSymbolAddress((void**)&w1_2, g_w1_2);
    cudaGetSymbolAddress((void**)&w2_2, g_w2_2);

    // smem opt-in (64 KB for the IN=128 configs)
    cudaFuncSetAttribute((const void*)k_fuse2<128, 128, 64, 4>,
                         cudaFuncAttributeMaxDynamicSharedMemorySize, 65536);
    cudaFuncSetAttribute((const void*)k_fuse2<128, 64, 64, 4>,
                         cudaFuncAttributeMaxDynamicSharedMemorySize, 65536);

    // CSR build
    k_zero_deg<<<(NN + 255) / 256, 256>>>();
    k_hist<<<(NE / 4 + 255) / 256, 256>>>(dst);
    k_scan<<<1, 1024>>>();
    k_scatter<<<(NE / 4 + 255) / 256, 256>>>(src, dst, attn);

    // fp16 weights
    k_convw<<<(128 * 128 + 255) / 256, 256>>>(W1_0, w1_0, 128 * 128);
    k_convw<<<(128 * 128 + 255) / 256, 256>>>(W2_0, w2_0, 128 * 128);
    k_convw<<<(128 * 64 + 255) / 256, 256>>>(W1_1, w1_1, 128 * 64);
    k_convw<<<(128 * 64 + 255) / 256, 256>>>(W2_1, w2_1, 128 * 64);
    k_convw<<<(64 * 32 + 255) / 256, 256>>>(W1_2, w1_2, 64 * 32);
    k_convw<<<(64 * 32 + 255) / 256, 256>>>(W2_2, w2_2, 64 * 32);

    // output cols [0,128) = x ; fp16 mirror of x
    k_copy_x<<<(NN * 32 + 255) / 256, 256>>>(x, out);

    const int aggBlocks = (NN * 32 + 255) / 256;
    const int tileGrid = (NN + 64 * 4 - 1) / (64 * 4);  // 391

    // layer 0: IN=128 -> OUT=128 (two BN=64 column slices)
    k_agg<4><<<aggBlocks, 256>>>(xh);
    {
        dim3 g(tileGrid, 2);
        k_fuse2<128, 128, 64, 4><<<g, 128, 65536>>>(x, 128, w1_0, b1_0, w2_0, b2_0, out, 128, hh);
    }
    // layer 1: IN=128 -> OUT=64
    k_agg<4><<<aggBlocks, 256>>>(hh);
    {
        dim3 g(tileGrid, 1);
        k_fuse2<128, 64, 64, 4><<<g, 128, 65536>>>(out + 128, 352, w1_1, b1_1, w2_1, b2_1, out, 256, hh);
    }
    // layer 2: IN=64 -> OUT=32
    k_agg<2><<<aggBlocks, 256>>>(hh);
    {
        dim3 g(tileGrid, 1);
        k_fuse2<64, 32, 32, 4><<<g, 128, 24576>>>(out + 256, 352, w1_2, b1_2, w2_2, b2_2, out, 320, nullptr);
    }
}

// round 13
// speedup vs baseline: 1.7521x; 1.3577x over previous
#include <cuda_runtime.h>
#include <cuda_fp16.h>
#include <mma.h>
#include <cstdint>

using namespace nvcuda;

#define NN 100000
#define NE 3200000

// ---------------- static device scratch (no allocations allowed) ----------------
__device__ int     g_deg[NN];
__device__ int     g_off[NN + 1];
__device__ int     g_cursor[NN];
__device__ int2    g_edge[NE];             // (src, bitcast(attn)) sorted by dst
__device__ __half2 g_xh[(size_t)NN * 64];  // fp16 mirror of x (128 cols)
__device__ __half2 g_hh[(size_t)NN * 64];  // fp16 mirror of current layer output
__device__ __half2 g_sh[(size_t)NN * 64];  // fp16 S = x + h_n
__device__ __half2 g_ph[(size_t)NN * 64];  // fp16 P = x * h_n
// fp16 weights
__device__ half g_w1_0[128 * 128];
__device__ half g_w2_0[128 * 128];
__device__ half g_w1_1[128 * 64];
__device__ half g_w2_1[128 * 64];
__device__ half g_w1_2[64 * 32];
__device__ half g_w2_2[64 * 32];

// ---------------- CSR build ----------------
__global__ void k_zero_deg() {
    int i = blockIdx.x * blockDim.x + threadIdx.x;
    if (i < NN) g_deg[i] = 0;
}

__global__ void k_hist(const int* __restrict__ dst) {
    int base = (blockIdx.x * blockDim.x + threadIdx.x) * 4;
    if (base + 3 < NE) {
        int4 d = *(const int4*)&dst[base];
        atomicAdd(&g_deg[d.x], 1);
        atomicAdd(&g_deg[d.y], 1);
        atomicAdd(&g_deg[d.z], 1);
        atomicAdd(&g_deg[d.w], 1);
    } else {
        for (int e = base; e < NE; e++) atomicAdd(&g_deg[dst[e]], 1);
    }
}

// single-block scan: each thread serially owns a contiguous chunk
__global__ void k_scan() {
    __shared__ int part[1024];
    int tid = threadIdx.x;
    const int CH = (NN + 1023) / 1024;
    int beg = tid * CH;
    int end = beg + CH < NN ? beg + CH : NN;
    int s = 0;
    for (int i = beg; i < end; i++) s += g_deg[i];
    part[tid] = s;
    __syncthreads();
    #pragma unroll
    for (int off = 1; off < 1024; off <<= 1) {
        int t = (tid >= off) ? part[tid - off] : 0;
        __syncthreads();
        part[tid] += t;
        __syncthreads();
    }
    int run = tid ? part[tid - 1] : 0;
    for (int i = beg; i < end; i++) {
        int d = g_deg[i];
        g_off[i] = run;
        g_cursor[i] = run;
        run += d;
    }
    if (tid == 1023) g_off[NN] = run;
}

__global__ void k_scatter(const int* __restrict__ src, const int* __restrict__ dst,
                          const float* __restrict__ attn) {
    int base = (blockIdx.x * blockDim.x + threadIdx.x) * 4;
    if (base + 3 < NE) {
        int4   s = *(const int4*)&src[base];
        int4   d = *(const int4*)&dst[base];
        float4 a = *(const float4*)&attn[base];
        int p0 = atomicAdd(&g_cursor[d.x], 1);
        int p1 = atomicAdd(&g_cursor[d.y], 1);
        int p2 = atomicAdd(&g_cursor[d.z], 1);
        int p3 = atomicAdd(&g_cursor[d.w], 1);
        g_edge[p0] = make_int2(s.x, __float_as_int(a.x));
        g_edge[p1] = make_int2(s.y, __float_as_int(a.y));
        g_edge[p2] = make_int2(s.z, __float_as_int(a.z));
        g_edge[p3] = make_int2(s.w, __float_as_int(a.w));
    } else {
        for (int e = base; e < NE; e++) {
            int p = atomicAdd(&g_cursor[dst[e]], 1);
            g_edge[p] = make_int2(src[e], __float_as_int(attn[e]));
        }
    }
}

// ---------------- weight fp32 -> fp16 ----------------
__global__ void k_convw(const float* __restrict__ W, half* __restrict__ Wh, int n) {
    int i = blockIdx.x * blockDim.x + threadIdx.x;
    if (i < n) Wh[i] = __float2half(W[i]);
}

// ---------------- copy x into output cols [0,128) + fp16 mirror ----------------
__global__ void k_copy_x(const float* __restrict__ x, float* __restrict__ out) {
    int t = blockIdx.x * blockDim.x + threadIdx.x;
    if (t < NN * 32) {
        int v = t >> 5, c = t & 31;
        float4 val = ((const float4*)(x + (size_t)v * 128))[c];
        ((float4*)(out + (size_t)v * 352))[c] = val;
        g_xh[(size_t)v * 64 + c * 2]     = __floats2half2_rn(val.x, val.y);
        g_xh[(size_t)v * 64 + c * 2 + 1] = __floats2half2_rn(val.z, val.w);
    }
}

// ---------------- aggregation: warp per node, CSR gather; emits fp16 S/P ----------------
// VEC=4 -> D=128 (lane covers 4 cols), VEC=2 -> D=64 (lane covers 2 cols)
template <int VEC>
__global__ void k_agg(const __half2* __restrict__ xin) {
    int gw = (blockIdx.x * blockDim.x + threadIdx.x) >> 5;
    if (gw >= NN) return;
    int lane = threadIdx.x & 31;
    int beg = g_off[gw], end = g_off[gw + 1];

    if (VEC == 4) {
        float4 acc = make_float4(0.f, 0.f, 0.f, 0.f);
        int e = beg;
        for (; e + 3 < end; e += 4) {
            int2 er0 = g_edge[e];
            int2 er1 = g_edge[e + 1];
            int2 er2 = g_edge[e + 2];
            int2 er3 = g_edge[e + 3];
            float2 raw0 = ((const float2*)(xin + (size_t)er0.x * 64))[lane];
            float2 raw1 = ((const float2*)(xin + (size_t)er1.x * 64))[lane];
            float2 raw2 = ((const float2*)(xin + (size_t)er2.x * 64))[lane];
            float2 raw3 = ((const float2*)(xin + (size_t)er3.x * 64))[lane];
            float a0 = __int_as_float(er0.y), a1 = __int_as_float(er1.y);
            float a2 = __int_as_float(er2.y), a3 = __int_as_float(er3.y);
            float2 p;
            p = __half22float2(*(const __half2*)&raw0.x);
            acc.x = fmaf(a0, p.x, acc.x); acc.y = fmaf(a0, p.y, acc.y);
            p = __half22float2(*(const __half2*)&raw0.y);
            acc.z = fmaf(a0, p.x, acc.z); acc.w = fmaf(a0, p.y, acc.w);
            p = __half22float2(*(const __half2*)&raw1.x);
            acc.x = fmaf(a1, p.x, acc.x); acc.y = fmaf(a1, p.y, acc.y);
            p = __half22float2(*(const __half2*)&raw1.y);
            acc.z = fmaf(a1, p.x, acc.z); acc.w = fmaf(a1, p.y, acc.w);
            p = __half22float2(*(const __half2*)&raw2.x);
            acc.x = fmaf(a2, p.x, acc.x); acc.y = fmaf(a2, p.y, acc.y);
            p = __half22float2(*(const __half2*)&raw2.y);
            acc.z = fmaf(a2, p.x, acc.z); acc.w = fmaf(a2, p.y, acc.w);
            p = __half22float2(*(const __half2*)&raw3.x);
            acc.x = fmaf(a3, p.x, acc.x); acc.y = fmaf(a3, p.y, acc.y);
            p = __half22float2(*(const __half2*)&raw3.y);
            acc.z = fmaf(a3, p.x, acc.z); acc.w = fmaf(a3, p.y, acc.w);
        }
        for (; e < end; e++) {
            int2 er = g_edge[e];
            float2 raw = ((const float2*)(xin + (size_t)er.x * 64))[lane];
            float a = __int_as_float(er.y);
            float2 p0 = __half22float2(*(const __half2*)&raw.x);
            float2 p1 = __half22float2(*(const __half2*)&raw.y);
            acc.x = fmaf(a, p0.x, acc.x); acc.y = fmaf(a, p0.y, acc.y);
            acc.z = fmaf(a, p1.x, acc.z); acc.w = fmaf(a, p1.y, acc.w);
        }
        // own-node features (fp16 mirror) -> S, P
        size_t idx = (size_t)gw * 64 + lane * 2;
        float2 x0 = __half22float2(xin[idx]);
        float2 x1 = __half22float2(xin[idx + 1]);
        g_sh[idx]     = __floats2half2_rn(x0.x + acc.x, x0.y + acc.y);
        g_sh[idx + 1] = __floats2half2_rn(x1.x + acc.z, x1.y + acc.w);
        g_ph[idx]     = __floats2half2_rn(x0.x * acc.x, x0.y * acc.y);
        g_ph[idx + 1] = __floats2half2_rn(x1.x * acc.z, x1.y * acc.w);
    } else {
        float2 acc = make_float2(0.f, 0.f);
        int e = beg;
        for (; e + 3 < end; e += 4) {
            int2 er0 = g_edge[e];
            int2 er1 = g_edge[e + 1];
            int2 er2 = g_edge[e + 2];
            int2 er3 = g_edge[e + 3];
            __half2 h0 = xin[(size_t)er0.x * 32 + lane];
            __half2 h1 = xin[(size_t)er1.x * 32 + lane];
            __half2 h2 = xin[(size_t)er2.x * 32 + lane];
            __half2 h3 = xin[(size_t)er3.x * 32 + lane];
            float2 p;
            p = __half22float2(h0); float a0 = __int_as_float(er0.y);
            acc.x = fmaf(a0, p.x, acc.x); acc.y = fmaf(a0, p.y, acc.y);
            p = __half22float2(h1); float a1 = __int_as_float(er1.y);
            acc.x = fmaf(a1, p.x, acc.x); acc.y = fmaf(a1, p.y, acc.y);
            p = __half22float2(h2); float a2 = __int_as_float(er2.y);
            acc.x = fmaf(a2, p.x, acc.x); acc.y = fmaf(a2, p.y, acc.y);
            p = __half22float2(h3); float a3 = __int_as_float(er3.y);
            acc.x = fmaf(a3, p.x, acc.x); acc.y = fmaf(a3, p.y, acc.y);
        }
        for (; e < end; e++) {
            int2 er = g_edge[e];
            __half2 h = xin[(size_t)er.x * 32 + lane];
            float a = __int_as_float(er.y);
            float2 p = __half22float2(h);
            acc.x = fmaf(a, p.x, acc.x); acc.y = fmaf(a, p.y, acc.y);
        }
        size_t idx = (size_t)gw * 32 + lane;
        float2 xv = __half22float2(xin[idx]);
        g_sh[idx] = __floats2half2_rn(xv.x + acc.x, xv.y + acc.y);
        g_ph[idx] = __floats2half2_rn(xv.x * acc.x, xv.y * acc.y);
    }
}

// ---------------- fused bi-interaction v3: padded smem, fp16 S/P inputs ----------------
// 256 threads / 8 warps (4 row-groups x 2 col-groups). Weights staged once per block
// (padded stride BN+8); NT node tiles of BM=64. All smem strides padded -> no LDSM conflicts.
template <int IN, int OUT, int BN, int NT>
__global__ void __launch_bounds__(256)
k_fuse3(const __half2* __restrict__ sh, const __half2* __restrict__ ph,
        const half* __restrict__ W1h, const float* __restrict__ b1,
        const half* __restrict__ W2h, const float* __restrict__ b2,
        float* __restrict__ out, int outcol, __half2* __restrict__ hh) {
    constexpr int BM = 64;
    constexpr int INP = IN + 8;            // operand smem stride (halfs)
    constexpr int BNP = BN + 8;            // weight smem stride (halfs)
    constexpr int BNQ = BN + 4;            // epilogue smem stride (floats)
    constexpr int CW = BN / 2;             // cols per warp
    constexpr int NF = CW / 16;

    extern __shared__ __align__(16) char sm[];
    half* sw1 = (half*)sm;                             // [IN][BNP]
    half* sw2 = sw1 + (size_t)IN * BNP;
    char* un  = sm + (size_t)2 * IN * BNP * sizeof(half);
    half*  s_s = (half*)un;                            // [BM][INP]
    half*  s_p = s_s + (size_t)BM * INP;
    float* o1  = (float*)un;                           // [BM][BNQ]
    float* o2  = o1 + (size_t)BM * BNQ;

    int tid = threadIdx.x;
    int wid = tid >> 5;
    int j0 = blockIdx.y * BN;
    int wm = wid >> 1;       // 0..3 -> 16-row group
    int wn = wid & 1;        // 0..1 -> CW-col group

    // ---- stage weight slice once (rows of BN halfs = BN/8 uint4) ----
    constexpr int RV = BN / 8;
    for (int i = tid; i < IN * RV; i += 256) {
        int r = i / RV, c = i % RV;
        ((uint4*)&sw1[(size_t)r * BNP])[c] = ((const uint4*)&W1h[(size_t)r * OUT + j0])[c];
        ((uint4*)&sw2[(size_t)r * BNP])[c] = ((const uint4*)&W2h[(size_t)r * OUT + j0])[c];
    }

    for (int t = 0; t < NT; t++) {
        int v0 = (blockIdx.x * NT + t) * BM;
        if (v0 >= NN) break;
        __syncthreads();   // weights staged / previous epilogue consumed

        // ---- stage S/P fp16 tiles (pure copies, rows of IN halfs = IN/8 uint4) ----
        constexpr int CV = IN / 8;
        for (int i = tid; i < BM * CV; i += 256) {
            int n = i / CV, c = i % CV;
            int v = v0 + n;
            uint4 vs = make_uint4(0, 0, 0, 0), vp = make_uint4(0, 0, 0, 0);
            if (v < NN) {
                vs = ((const uint4*)(sh + (size_t)v * (IN / 2)))[c];
                vp = ((const uint4*)(ph + (size_t)v * (IN / 2)))[c];
            }
            ((uint4*)&s_s[(size_t)n * INP])[c] = vs;
            ((uint4*)&s_p[(size_t)n * INP])[c] = vp;
        }
        __syncthreads();

        // ---- mainloop (all smem, padded strides) ----
        wmma::fragment<wmma::accumulator, 16, 16, 16, float> acc1[NF], acc2[NF];
        #pragma unroll
        for (int ni = 0; ni < NF; ni++) {
            wmma::fill_fragment(acc1[ni], 0.f);
            wmma::fill_fragment(acc2[ni], 0.f);
        }
        for (int kc = 0; kc < IN; kc += 16) {
            wmma::fragment<wmma::matrix_a, 16, 16, 16, half, wmma::row_major> a1, a2;
            wmma::load_matrix_sync(a1, &s_s[(size_t)(wm * 16) * INP + kc], INP);
            wmma::load_matrix_sync(a2, &s_p[(size_t)(wm * 16) * INP + kc], INP);
            #pragma unroll
            for (int ni = 0; ni < NF; ni++) {
                int c = wn * CW + ni * 16;
                wmma::fragment<wmma::matrix_b, 16, 16, 16, half, wmma::row_major> bf1, bf2;
                wmma::load_matrix_sync(bf1, &sw1[(size_t)kc * BNP + c], BNP);
                wmma::load_matrix_sync(bf2, &sw2[(size_t)kc * BNP + c], BNP);
                wmma::mma_sync(acc1[ni], a1, bf1, acc1[ni]);
                wmma::mma_sync(acc2[ni], a2, bf2, acc2[ni]);
            }
        }

        // ---- epilogue via padded smem ----
        __syncthreads();   // operand tiles dead
        #pragma unroll
        for (int ni = 0; ni < NF; ni++) {
            int c = wn * CW + ni * 16;
            wmma::store_matrix_sync(&o1[(size_t)(wm * 16) * BNQ + c], acc1[ni], BNQ, wmma::mem_row_major);
            wmma::store_matrix_sync(&o2[(size_t)(wm * 16) * BNQ + c], acc2[ni], BNQ, wmma::mem_row_major);
        }
        __syncthreads();

        for (int i = tid; i < BM * (BN / 2); i += 256) {
            int n = i / (BN / 2), j2 = i % (BN / 2);
            int v = v0 + n;
            if (v < NN) {
                int j = j2 * 2;
                float r1a = o1[(size_t)n * BNQ + j]     + b1[j0 + j];
                float r1b = o1[(size_t)n * BNQ + j + 1] + b1[j0 + j + 1];
                float r2a = o2[(size_t)n * BNQ + j]     + b2[j0 + j];
                float r2b = o2[(size_t)n * BNQ + j + 1] + b2[j0 + j + 1];
                r1a = r1a > 0.f ? r1a : 0.01f * r1a;
                r1b = r1b > 0.f ? r1b : 0.01f * r1b;
                r2a = r2a > 0.f ? r2a : 0.01f * r2a;
                r2b = r2b > 0.f ? r2b : 0.01f * r2b;
                float ra = r1a + r2a, rb = r1b + r2b;
                *(float2*)&out[(size_t)v * 352 + outcol + j0 + j] = make_float2(ra, rb);
                if (hh) hh[(size_t)v * (OUT / 2) + ((j0 + j) >> 1)] = __floats2half2_rn(ra, rb);
            }
        }
    }
}

// ---------------- launch ----------------
extern "C" void kernel_launch(void* const* d_in, const int* in_sizes, int n_in,
                              void* d_out, int out_size) {
    const float* x    = (const float*)d_in[0];
    const int*   src  = (const int*)d_in[1];
    const int*   dst  = (const int*)d_in[2];
    const float* attn = (const float*)d_in[3];
    const float* W1_0 = (const float*)d_in[4];
    const float* b1_0 = (const float*)d_in[5];
    const float* W2_0 = (const float*)d_in[6];
    const float* b2_0 = (const float*)d_in[7];
    const float* W1_1 = (const float*)d_in[8];
    const float* b1_1 = (const float*)d_in[9];
    const float* W2_1 = (const float*)d_in[10];
    const float* b2_1 = (const float*)d_in[11];
    const float* W1_2 = (const float*)d_in[12];
    const float* b1_2 = (const float*)d_in[13];
    const float* W2_2 = (const float*)d_in[14];
    const float* b2_2 = (const float*)d_in[15];
    float* out = (float*)d_out;

    __half2 *xh, *hh, *sh, *ph;
    half *w1_0, *w2_0, *w1_1, *w2_1, *w1_2, *w2_2;
    cudaGetSymbolAddress((void**)&xh, g_xh);
    cudaGetSymbolAddress((void**)&hh, g_hh);
    cudaGetSymbolAddress((void**)&sh, g_sh);
    cudaGetSymbolAddress((void**)&ph, g_ph);
    cudaGetSymbolAddress((void**)&w1_0, g_w1_0);
    cudaGetSymbolAddress((void**)&w2_0, g_w2_0);
    cudaGetSymbolAddress((void**)&w1_1, g_w1_1);
    cudaGetSymbolAddress((void**)&w2_1, g_w2_1);
    cudaGetSymbolAddress((void**)&w1_2, g_w1_2);
    cudaGetSymbolAddress((void**)&w2_2, g_w2_2);

    // smem sizes: weights 2*IN*(BN+8)*2 + union(oper, epi)
    const int SM0 = 2 * 128 * 72 * 2 + 2 * 64 * 136 * 2;   // 36864 + 34816 = 71680
    const int SM2 = 2 * 64 * 40 * 2 + 2 * 64 * 72 * 2;     // 10240 + 18432 = 28672
    cudaFuncSetAttribute((const void*)k_fuse3<128, 128, 64, 8>,
                         cudaFuncAttributeMaxDynamicSharedMemorySize, SM0);
    cudaFuncSetAttribute((const void*)k_fuse3<128, 64, 64, 4>,
                         cudaFuncAttributeMaxDynamicSharedMemorySize, SM0);
    cudaFuncSetAttribute((const void*)k_fuse3<64, 32, 32, 2>,
                         cudaFuncAttributeMaxDynamicSharedMemorySize, SM2);

    // CSR build
    k_zero_deg<<<(NN + 255) / 256, 256>>>();
    k_hist<<<(NE / 4 + 255) / 256, 256>>>(dst);
    k_scan<<<1, 1024>>>();
    k_scatter<<<(NE / 4 + 255) / 256, 256>>>(src, dst, attn);

    // fp16 weights
    k_convw<<<(128 * 128 + 255) / 256, 256>>>(W1_0, w1_0, 128 * 128);
    k_convw<<<(128 * 128 + 255) / 256, 256>>>(W2_0, w2_0, 128 * 128);
    k_convw<<<(128 * 64 + 255) / 256, 256>>>(W1_1, w1_1, 128 * 64);
    k_convw<<<(128 * 64 + 255) / 256, 256>>>(W2_1, w2_1, 128 * 64);
    k_convw<<<(64 * 32 + 255) / 256, 256>>>(W1_2, w1_2, 64 * 32);
    k_convw<<<(64 * 32 + 255) / 256, 256>>>(W2_2, w2_2, 64 * 32);

    // output cols [0,128) = x ; fp16 mirror of x
    k_copy_x<<<(NN * 32 + 255) / 256, 256>>>(x, out);

    const int aggBlocks = (NN * 32 + 255) / 256;

    // layer 0: IN=128 -> OUT=128 (two BN=64 slices), NT=8 -> 196 x-blocks
    k_agg<4><<<aggBlocks, 256>>>(xh);
    {
        dim3 g((NN + 64 * 8 - 1) / (64 * 8), 2);
        k_fuse3<128, 128, 64, 8><<<g, 256, SM0>>>(sh, ph, w1_0, b1_0, w2_0, b2_0, out, 128, hh);
    }
    // layer 1: IN=128 -> OUT=64, NT=4 -> 391 x-blocks
    k_agg<4><<<aggBlocks, 256>>>(hh);
    {
        dim3 g((NN + 64 * 4 - 1) / (64 * 4), 1);
        k_fuse3<128, 64, 64, 4><<<g, 256, SM0>>>(sh, ph, w1_1, b1_1, w2_1, b2_1, out, 256, hh);
    }
    // layer 2: IN=64 -> OUT=32, NT=2 -> 782 x-blocks
    k_agg<2><<<aggBlocks, 256>>>(hh);
    {
        dim3 g((NN + 64 * 2 - 1) / (64 * 2), 1);
        k_fuse3<64, 32, 32, 2><<<g, 256, SM2>>>(sh, ph, w1_2, b1_2, w2_2, b2_2, out, 320, nullptr);
    }
}

// round 17
// speedup vs baseline: 2.3756x; 1.3559x over previous
#include <cuda_runtime.h>
#include <cuda_fp16.h>
#include <mma.h>
#include <cstdint>

using namespace nvcuda;

#define NN 100000
#define NE 3200000
#define NB 98   // ceil(NN / 1024)

// ---------------- static device scratch (no allocations allowed) ----------------
__device__ int     g_deg[NN];
__device__ int     g_off[NN + 1];
__device__ int     g_cursor[NN];
__device__ int     g_part[NB];
__device__ int2    g_edge[NE];             // (src, bitcast(attn)) sorted by dst
__device__ __half2 g_xh[(size_t)NN * 64];  // fp16 mirror of x (128 cols)
__device__ __half2 g_hh[(size_t)NN * 64];  // fp16 mirror of current layer output
__device__ __half2 g_sh[(size_t)NN * 64];  // fp16 S = x + h_n
__device__ __half2 g_ph[(size_t)NN * 64];  // fp16 P = x * h_n
// fp16 weights (contiguous pool)
__device__ half g_wpool[2 * (128 * 128 + 128 * 64 + 64 * 32)];

// ---------------- CSR build ----------------
__global__ void k_zero_deg() {
    int i = blockIdx.x * blockDim.x + threadIdx.x;
    if (i < NN) g_deg[i] = 0;
}

__global__ void k_hist(const int* __restrict__ dst) {
    int base = (blockIdx.x * blockDim.x + threadIdx.x) * 4;
    if (base + 3 < NE) {
        int4 d = *(const int4*)&dst[base];
        atomicAdd(&g_deg[d.x], 1);
        atomicAdd(&g_deg[d.y], 1);
        atomicAdd(&g_deg[d.z], 1);
        atomicAdd(&g_deg[d.w], 1);
    } else {
        for (int e = base; e < NE; e++) atomicAdd(&g_deg[dst[e]], 1);
    }
}

// ---- parallel scan, phase A: per-block (1024-chunk) sums ----
__global__ void k_scanA() {
    __shared__ int red[1024];
    int t = threadIdx.x;
    int i = blockIdx.x * 1024 + t;
    red[t] = (i < NN) ? g_deg[i] : 0;
    __syncthreads();
    #pragma unroll
    for (int off = 512; off > 0; off >>= 1) {
        if (t < off) red[t] += red[t + off];
        __syncthreads();
    }
    if (t == 0) g_part[blockIdx.x] = red[0];
}

// ---- phase B: 1 small block scans the NB partials -> exclusive; writes g_off[NN] ----
__global__ void k_scanB() {
    __shared__ int sm[128];
    int t = threadIdx.x;
    int v = (t < NB) ? g_part[t] : 0;
    sm[t] = v;
    __syncthreads();
    #pragma unroll
    for (int off = 1; off < 128; off <<= 1) {
        int u = (t >= off) ? sm[t - off] : 0;
        __syncthreads();
        sm[t] += u;
        __syncthreads();
    }
    if (t < NB) g_part[t] = sm[t] - v;   // exclusive prefix
    if (t == 0) g_off[NN] = NE;          // degrees sum to NE exactly
}

// ---- phase C: per-block exclusive scan + base; writes g_off / g_cursor ----
__global__ void k_scanC() {
    __shared__ int sm[1024];
    int t = threadIdx.x;
    int i = blockIdx.x * 1024 + t;
    int v = (i < NN) ? g_deg[i] : 0;
    sm[t] = v;
    __syncthreads();
    #pragma unroll
    for (int off = 1; off < 1024; off <<= 1) {
        int u = (t >= off) ? sm[t - off] : 0;
        __syncthreads();
        sm[t] += u;
        __syncthreads();
    }
    if (i < NN) {
        int ex = g_part[blockIdx.x] + sm[t] - v;
        g_off[i] = ex;
        g_cursor[i] = ex;
    }
}

__global__ void k_scatter(const int* __restrict__ src, const int* __restrict__ dst,
                          const float* __restrict__ attn) {
    int base = (blockIdx.x * blockDim.x + threadIdx.x) * 4;
    if (base + 3 < NE) {
        int4   s = *(const int4*)&src[base];
        int4   d = *(const int4*)&dst[base];
        float4 a = *(const float4*)&attn[base];
        int p0 = atomicAdd(&g_cursor[d.x], 1);
        int p1 = atomicAdd(&g_cursor[d.y], 1);
        int p2 = atomicAdd(&g_cursor[d.z], 1);
        int p3 = atomicAdd(&g_cursor[d.w], 1);
        g_edge[p0] = make_int2(s.x, __float_as_int(a.x));
        g_edge[p1] = make_int2(s.y, __float_as_int(a.y));
        g_edge[p2] = make_int2(s.z, __float_as_int(a.z));
        g_edge[p3] = make_int2(s.w, __float_as_int(a.w));
    } else {
        for (int e = base; e < NE; e++) {
            int p = atomicAdd(&g_cursor[dst[e]], 1);
            g_edge[p] = make_int2(src[e], __float_as_int(attn[e]));
        }
    }
}

// ---------------- merged weight fp32 -> fp16 (6 arrays, one kernel) ----------------
__global__ void k_convw_all(const float* __restrict__ W1_0, const float* __restrict__ W2_0,
                            const float* __restrict__ W1_1, const float* __restrict__ W2_1,
                            const float* __restrict__ W1_2, const float* __restrict__ W2_2) {
    const int N0 = 128 * 128, N1 = 128 * 64, N2 = 64 * 32;
    int i = blockIdx.x * blockDim.x + threadIdx.x;
    int total = 2 * (N0 + N1 + N2);
    if (i >= total) return;
    const float* srcs[6] = {W1_0, W2_0, W1_1, W2_1, W1_2, W2_2};
    const int sizes[6] = {N0, N0, N1, N1, N2, N2};
    int rem = i;
    #pragma unroll
    for (int a = 0; a < 6; a++) {
        if (rem < sizes[a]) { g_wpool[i] = __float2half(srcs[a][rem]); return; }
        rem -= sizes[a];
    }
}

// ---------------- copy x into output cols [0,128) + fp16 mirror ----------------
__global__ void k_copy_x(const float* __restrict__ x, float* __restrict__ out) {
    int t = blockIdx.x * blockDim.x + threadIdx.x;
    if (t < NN * 32) {
        int v = t >> 5, c = t & 31;
        float4 val = ((const float4*)(x + (size_t)v * 128))[c];
        ((float4*)(out + (size_t)v * 352))[c] = val;
        g_xh[(size_t)v * 64 + c * 2]     = __floats2half2_rn(val.x, val.y);
        g_xh[(size_t)v * 64 + c * 2 + 1] = __floats2half2_rn(val.z, val.w);
    }
}

// ---------------- aggregation: warp per node, CSR gather; emits fp16 S/P ----------------
template <int VEC>
__global__ void k_agg(const __half2* __restrict__ xin) {
    int gw = (blockIdx.x * blockDim.x + threadIdx.x) >> 5;
    if (gw >= NN) return;
    int lane = threadIdx.x & 31;
    int beg = g_off[gw], end = g_off[gw + 1];

    if (VEC == 4) {
        float4 acc = make_float4(0.f, 0.f, 0.f, 0.f);
        int e = beg;
        for (; e + 3 < end; e += 4) {
            int2 er0 = g_edge[e];
            int2 er1 = g_edge[e + 1];
            int2 er2 = g_edge[e + 2];
            int2 er3 = g_edge[e + 3];
            float2 raw0 = ((const float2*)(xin + (size_t)er0.x * 64))[lane];
            float2 raw1 = ((const float2*)(xin + (size_t)er1.x * 64))[lane];
            float2 raw2 = ((const float2*)(xin + (size_t)er2.x * 64))[lane];
            float2 raw3 = ((const float2*)(xin + (size_t)er3.x * 64))[lane];
            float a0 = __int_as_float(er0.y), a1 = __int_as_float(er1.y);
            float a2 = __int_as_float(er2.y), a3 = __int_as_float(er3.y);
            float2 p;
            p = __half22float2(*(const __half2*)&raw0.x);
            acc.x = fmaf(a0, p.x, acc.x); acc.y = fmaf(a0, p.y, acc.y);
            p = __half22float2(*(const __half2*)&raw0.y);
            acc.z = fmaf(a0, p.x, acc.z); acc.w = fmaf(a0, p.y, acc.w);
            p = __half22float2(*(const __half2*)&raw1.x);
            acc.x = fmaf(a1, p.x, acc.x); acc.y = fmaf(a1, p.y, acc.y);
            p = __half22float2(*(const __half2*)&raw1.y);
            acc.z = fmaf(a1, p.x, acc.z); acc.w = fmaf(a1, p.y, acc.w);
            p = __half22float2(*(const __half2*)&raw2.x);
            acc.x = fmaf(a2, p.x, acc.x); acc.y = fmaf(a2, p.y, acc.y);
            p = __half22float2(*(const __half2*)&raw2.y);
            acc.z = fmaf(a2, p.x, acc.z); acc.w = fmaf(a2, p.y, acc.w);
            p = __half22float2(*(const __half2*)&raw3.x);
            acc.x = fmaf(a3, p.x, acc.x); acc.y = fmaf(a3, p.y, acc.y);
            p = __half22float2(*(const __half2*)&raw3.y);
            acc.z = fmaf(a3, p.x, acc.z); acc.w = fmaf(a3, p.y, acc.w);
        }
        for (; e < end; e++) {
            int2 er = g_edge[e];
            float2 raw = ((const float2*)(xin + (size_t)er.x * 64))[lane];
            float a = __int_as_float(er.y);
            float2 p0 = __half22float2(*(const __half2*)&raw.x);
            float2 p1 = __half22float2(*(const __half2*)&raw.y);
            acc.x = fmaf(a, p0.x, acc.x); acc.y = fmaf(a, p0.y, acc.y);
            acc.z = fmaf(a, p1.x, acc.z); acc.w = fmaf(a, p1.y, acc.w);
        }
        // own-node features (fp16 mirror) -> S, P
        size_t idx = (size_t)gw * 64 + lane * 2;
        float2 x0 = __half22float2(xin[idx]);
        float2 x1 = __half22float2(xin[idx + 1]);
        g_sh[idx]     = __floats2half2_rn(x0.x + acc.x, x0.y + acc.y);
        g_sh[idx + 1] = __floats2half2_rn(x1.x + acc.z, x1.y + acc.w);
        g_ph[idx]     = __floats2half2_rn(x0.x * acc.x, x0.y * acc.y);
        g_ph[idx + 1] = __floats2half2_rn(x1.x * acc.z, x1.y * acc.w);
    } else {
        float2 acc = make_float2(0.f, 0.f);
        int e = beg;
        for (; e + 3 < end; e += 4) {
            int2 er0 = g_edge[e];
            int2 er1 = g_edge[e + 1];
            int2 er2 = g_edge[e + 2];
            int2 er3 = g_edge[e + 3];
            __half2 h0 = xin[(size_t)er0.x * 32 + lane];
            __half2 h1 = xin[(size_t)er1.x * 32 + lane];
            __half2 h2 = xin[(size_t)er2.x * 32 + lane];
            __half2 h3 = xin[(size_t)er3.x * 32 + lane];
            float2 p;
            p = __half22float2(h0); float a0 = __int_as_float(er0.y);
            acc.x = fmaf(a0, p.x, acc.x); acc.y = fmaf(a0, p.y, acc.y);
            p = __half22float2(h1); float a1 = __int_as_float(er1.y);
            acc.x = fmaf(a1, p.x, acc.x); acc.y = fmaf(a1, p.y, acc.y);
            p = __half22float2(h2); float a2 = __int_as_float(er2.y);
            acc.x = fmaf(a2, p.x, acc.x); acc.y = fmaf(a2, p.y, acc.y);
            p = __half22float2(h3); float a3 = __int_as_float(er3.y);
            acc.x = fmaf(a3, p.x, acc.x); acc.y = fmaf(a3, p.y, acc.y);
        }
        for (; e < end; e++) {
            int2 er = g_edge[e];
            __half2 h = xin[(size_t)er.x * 32 + lane];
            float a = __int_as_float(er.y);
            float2 p = __half22float2(h);
            acc.x = fmaf(a, p.x, acc.x); acc.y = fmaf(a, p.y, acc.y);
        }
        size_t idx = (size_t)gw * 32 + lane;
        float2 xv = __half22float2(xin[idx]);
        g_sh[idx] = __floats2half2_rn(xv.x + acc.x, xv.y + acc.y);
        g_ph[idx] = __floats2half2_rn(xv.x * acc.x, xv.y * acc.y);
    }
}

// ---------------- fused bi-interaction v3: padded smem, fp16 S/P inputs ----------------
// 256 threads / 8 warps (4 row-groups x 2 col-groups). Weights staged once per block
// (padded stride BN+8); NT node tiles of BM=64. All smem strides padded -> no LDSM conflicts.
template <int IN, int OUT, int BN, int NT>
__global__ void __launch_bounds__(256)
k_fuse3(const __half2* __restrict__ sh, const __half2* __restrict__ ph,
        const half* __restrict__ W1h, const float* __restrict__ b1,
        const half* __restrict__ W2h, const float* __restrict__ b2,
        float* __restrict__ out, int outcol, __half2* __restrict__ hh) {
    constexpr int BM = 64;
    constexpr int INP = IN + 8;            // operand smem stride (halfs)
    constexpr int BNP = BN + 8;            // weight smem stride (halfs)
    constexpr int BNQ = BN + 4;            // epilogue smem stride (floats)
    constexpr int CW = BN / 2;             // cols per warp
    constexpr int NF = CW / 16;

    extern __shared__ __align__(16) char sm[];
    half* sw1 = (half*)sm;                             // [IN][BNP]
    half* sw2 = sw1 + (size_t)IN * BNP;
    char* un  = sm + (size_t)2 * IN * BNP * sizeof(half);
    half*  s_s = (half*)un;                            // [BM][INP]
    half*  s_p = s_s + (size_t)BM * INP;
    float* o1  = (float*)un;                           // [BM][BNQ]
    float* o2  = o1 + (size_t)BM * BNQ;

    int tid = threadIdx.x;
    int wid = tid >> 5;
    int j0 = blockIdx.y * BN;
    int wm = wid >> 1;       // 0..3 -> 16-row group
    int wn = wid & 1;        // 0..1 -> CW-col group

    // ---- stage weight slice once (rows of BN halfs = BN/8 uint4) ----
    constexpr int RV = BN / 8;
    for (int i = tid; i < IN * RV; i += 256) {
        int r = i / RV, c = i % RV;
        ((uint4*)&sw1[(size_t)r * BNP])[c] = ((const uint4*)&W1h[(size_t)r * OUT + j0])[c];
        ((uint4*)&sw2[(size_t)r * BNP])[c] = ((const uint4*)&W2h[(size_t)r * OUT + j0])[c];
    }

    for (int t = 0; t < NT; t++) {
        int v0 = (blockIdx.x * NT + t) * BM;
        if (v0 >= NN) break;
        __syncthreads();   // weights staged / previous epilogue consumed

        // ---- stage S/P fp16 tiles (pure copies, rows of IN halfs = IN/8 uint4) ----
        constexpr int CV = IN / 8;
        for (int i = tid; i < BM * CV; i += 256) {
            int n = i / CV, c = i % CV;
            int v = v0 + n;
            uint4 vs = make_uint4(0, 0, 0, 0), vp = make_uint4(0, 0, 0, 0);
            if (v < NN) {
                vs = ((const uint4*)(sh + (size_t)v * (IN / 2)))[c];
                vp = ((const uint4*)(ph + (size_t)v * (IN / 2)))[c];
            }
            ((uint4*)&s_s[(size_t)n * INP])[c] = vs;
            ((uint4*)&s_p[(size_t)n * INP])[c] = vp;
        }
        __syncthreads();

        // ---- mainloop (all smem, padded strides) ----
        wmma::fragment<wmma::accumulator, 16, 16, 16, float> acc1[NF], acc2[NF];
        #pragma unroll
        for (int ni = 0; ni < NF; ni++) {
            wmma::fill_fragment(acc1[ni], 0.f);
            wmma::fill_fragment(acc2[ni], 0.f);
        }
        for (int kc = 0; kc < IN; kc += 16) {
            wmma::fragment<wmma::matrix_a, 16, 16, 16, half, wmma::row_major> a1, a2;
            wmma::load_matrix_sync(a1, &s_s[(size_t)(wm * 16) * INP + kc], INP);
            wmma::load_matrix_sync(a2, &s_p[(size_t)(wm * 16) * INP + kc], INP);
            #pragma unroll
            for (int ni = 0; ni < NF; ni++) {
                int c = wn * CW + ni * 16;
                wmma::fragment<wmma::matrix_b, 16, 16, 16, half, wmma::row_major> bf1, bf2;
                wmma::load_matrix_sync(bf1, &sw1[(size_t)kc * BNP + c], BNP);
                wmma::load_matrix_sync(bf2, &sw2[(size_t)kc * BNP + c], BNP);
                wmma::mma_sync(acc1[ni], a1, bf1, acc1[ni]);
                wmma::mma_sync(acc2[ni], a2, bf2, acc2[ni]);
            }
        }

        // ---- epilogue via padded smem ----
        __syncthreads();   // operand tiles dead
        #pragma unroll
        for (int ni = 0; ni < NF; ni++) {
            int c = wn * CW + ni * 16;
            wmma::store_matrix_sync(&o1[(size_t)(wm * 16) * BNQ + c], acc1[ni], BNQ, wmma::mem_row_major);
            wmma::store_matrix_sync(&o2[(size_t)(wm * 16) * BNQ + c], acc2[ni], BNQ, wmma::mem_row_major);
        }
        __syncthreads();

        for (int i = tid; i < BM * (BN / 2); i += 256) {
            int n = i / (BN / 2), j2 = i % (BN / 2);
            int v = v0 + n;
            if (v < NN) {
                int j = j2 * 2;
                float r1a = o1[(size_t)n * BNQ + j]     + b1[j0 + j];
                float r1b = o1[(size_t)n * BNQ + j + 1] + b1[j0 + j + 1];
                float r2a = o2[(size_t)n * BNQ + j]     + b2[j0 + j];
                float r2b = o2[(size_t)n * BNQ + j + 1] + b2[j0 + j + 1];
                r1a = r1a > 0.f ? r1a : 0.01f * r1a;
                r1b = r1b > 0.f ? r1b : 0.01f * r1b;
                r2a = r2a > 0.f ? r2a : 0.01f * r2a;
                r2b = r2b > 0.f ? r2b : 0.01f * r2b;
                float ra = r1a + r2a, rb = r1b + r2b;
                *(float2*)&out[(size_t)v * 352 + outcol + j0 + j] = make_float2(ra, rb);
                if (hh) hh[(size_t)v * (OUT / 2) + ((j0 + j) >> 1)] = __floats2half2_rn(ra, rb);
            }
        }
    }
}

// ---------------- launch ----------------
extern "C" void kernel_launch(void* const* d_in, const int* in_sizes, int n_in,
                              void* d_out, int out_size) {
    const float* x    = (const float*)d_in[0];
    const int*   src  = (const int*)d_in[1];
    const int*   dst  = (const int*)d_in[2];
    const float* attn = (const float*)d_in[3];
    const float* W1_0 = (const float*)d_in[4];
    const float* b1_0 = (const float*)d_in[5];
    const float* W2_0 = (const float*)d_in[6];
    const float* b2_0 = (const float*)d_in[7];
    const float* W1_1 = (const float*)d_in[8];
    const float* b1_1 = (const float*)d_in[9];
    const float* W2_1 = (const float*)d_in[10];
    const float* b2_1 = (const float*)d_in[11];
    const float* W1_2 = (const float*)d_in[12];
    const float* b1_2 = (const float*)d_in[13];
    const float* W2_2 = (const float*)d_in[14];
    const float* b2_2 = (const float*)d_in[15];
    float* out = (float*)d_out;

    __half2 *xh, *hh, *sh, *ph;
    half *wpool;
    cudaGetSymbolAddress((void**)&xh, g_xh);
    cudaGetSymbolAddress((void**)&hh, g_hh);
    cudaGetSymbolAddress((void**)&sh, g_sh);
    cudaGetSymbolAddress((void**)&ph, g_ph);
    cudaGetSymbolAddress((void**)&wpool, g_wpool);
    const int N0 = 128 * 128, N1 = 128 * 64, N2 = 64 * 32;
    half* w1_0 = wpool;
    half* w2_0 = w1_0 + N0;
    half* w1_1 = w2_0 + N0;
    half* w2_1 = w1_1 + N1;
    half* w1_2 = w2_1 + N1;
    half* w2_2 = w1_2 + N2;

    // smem sizes: weights 2*IN*(BN+8)*2 + union(oper, epi)
    const int SM0 = 2 * 128 * 72 * 2 + 2 * 64 * 136 * 2;   // 36864 + 34816 = 71680
    const int SM2 = 2 * 64 * 40 * 2 + 2 * 64 * 72 * 2;     // 10240 + 18432 = 28672
    cudaFuncSetAttribute((const void*)k_fuse3<128, 128, 64, 8>,
                         cudaFuncAttributeMaxDynamicSharedMemorySize, SM0);
    cudaFuncSetAttribute((const void*)k_fuse3<128, 64, 64, 4>,
                         cudaFuncAttributeMaxDynamicSharedMemorySize, SM0);
    cudaFuncSetAttribute((const void*)k_fuse3<64, 32, 32, 2>,
                         cudaFuncAttributeMaxDynamicSharedMemorySize, SM2);

    // CSR build (parallel 3-phase scan)
    k_zero_deg<<<(NN + 255) / 256, 256>>>();
    k_hist<<<(NE / 4 + 255) / 256, 256>>>(dst);
    k_scanA<<<NB, 1024>>>();
    k_scanB<<<1, 128>>>();
    k_scanC<<<NB, 1024>>>();
    k_scatter<<<(NE / 4 + 255) / 256, 256>>>(src, dst, attn);

    // fp16 weights (one kernel)
    k_convw_all<<<(2 * (N0 + N1 + N2) + 255) / 256, 256>>>(W1_0, W2_0, W1_1, W2_1, W1_2, W2_2);

    // output cols [0,128) = x ; fp16 mirror of x
    k_copy_x<<<(NN * 32 + 255) / 256, 256>>>(x, out);

    const int aggBlocks = (NN * 32 + 255) / 256;

    // layer 0: IN=128 -> OUT=128 (two BN=64 slices), NT=8 -> 196 x-blocks
    k_agg<4><<<aggBlocks, 256>>>(xh);
    {
        dim3 g((NN + 64 * 8 - 1) / (64 * 8), 2);
        k_fuse3<128, 128, 64, 8><<<g, 256, SM0>>>(sh, ph, w1_0, b1_0, w2_0, b2_0, out, 128, hh);
    }
    // layer 1: IN=128 -> OUT=64, NT=4 -> 391 x-blocks
    k_agg<4><<<aggBlocks, 256>>>(hh);
    {
        dim3 g((NN + 64 * 4 - 1) / (64 * 4), 1);
        k_fuse3<128, 64, 64, 4><<<g, 256, SM0>>>(sh, ph, w1_1, b1_1, w2_1, b2_1, out, 256, hh);
    }
    // layer 2: IN=64 -> OUT=32, NT=2 -> 782 x-blocks
    k_agg<2><<<aggBlocks, 256>>>(hh);
    {
        dim3 g((NN + 64 * 2 - 1) / (64 * 2), 1);
        k_fuse3<64, 32, 32, 2><<<g, 256, SM2>>>(sh, ph, w1_2, b1_2, w2_2, b2_2, out, 320, nullptr);
    }
}